// round 15
// baseline (speedup 1.0000x reference)
#include <cuda_runtime.h>
#include <cuda_fp16.h>
#include <cstdint>
#include <cstddef>

// ---------------------------------------------------------------------------
// MultiheadedAttention2 (batch-axis softmax) — v15: fp16 mma.sync GEMMs.
//   att = softmax_b( SCALE*(qM@key^T + u + w) ),  qM = query@M, M = Wq^T Wk
//   out = att@vpT'^T + bo,   vpT'[e][s] = (P@value^T)[e][s] + wv[e]
//   (wv fold replaces the rowsum(att) (x) wv term exactly: att@(1 wv^T) = rs(x)wv)
// TM-templated tiles (128x256 / 64x256) to kill wave tails; merged M&P launch.
// fp16 operands / fp32 accum; u/w/c/bo exact fp32.
// ---------------------------------------------------------------------------

#define B_SZ 8
#define T_SZ 2048
#define E_SZ 512
#define HE_SZ 4096
#define SCALE_F 0.04419417382415922f  // 512^-0.5

#define STAGES 4
#define ROWH 72                         // padded row: 72 halves = 144 B
#define NSPLIT 8
#define NCH 64

#define GSMEM_128 (STAGES * (128 + 256) * ROWH * 2)  // 221184
#define GSMEM_64  (STAGES * (64 + 256) * ROWH * 2)   // 184320

// Scratch (device globals; allocation-free rule)
__device__ __half g_atth[(size_t)B_SZ * T_SZ * T_SZ];   // logits -> att (fp16)
__device__ __half g_qh[(size_t)B_SZ * T_SZ * E_SZ];
__device__ __half g_kh[(size_t)B_SZ * T_SZ * E_SZ];
__device__ __half g_vh[(size_t)B_SZ * T_SZ * E_SZ];
__device__ __half g_Woh[(size_t)E_SZ * HE_SZ];
__device__ __half g_WqT[(size_t)E_SZ * HE_SZ];
__device__ __half g_WkT[(size_t)E_SZ * HE_SZ];
__device__ __half g_WvT[(size_t)E_SZ * HE_SZ];
__device__ __half g_MTh[(size_t)E_SZ * E_SZ];
__device__ __half g_Ph[(size_t)E_SZ * E_SZ];
__device__ __half g_qMh[(size_t)B_SZ * T_SZ * E_SZ];
__device__ __half g_vpTh[(size_t)B_SZ * E_SZ * T_SZ];
__device__ float  g_part[(size_t)2 * NSPLIT * E_SZ * E_SZ];
__device__ float  g_cpart[(size_t)2 * NCH * E_SZ];
__device__ float  g_a1[E_SZ];
__device__ float  g_a2[E_SZ];
__device__ float  g_wv[E_SZ];
__device__ float  g_c[1];
__device__ float  g_u[(size_t)B_SZ * T_SZ];
__device__ float  g_w[(size_t)B_SZ * T_SZ];

static __device__ __forceinline__ void mma_f16(float* c, const uint32_t* a, const uint32_t* b) {
    asm volatile(
        "mma.sync.aligned.m16n8k16.row.col.f32.f16.f16.f32 "
        "{%0,%1,%2,%3}, {%4,%5,%6,%7}, {%8,%9}, {%0,%1,%2,%3};\n"
        : "+f"(c[0]), "+f"(c[1]), "+f"(c[2]), "+f"(c[3])
        : "r"(a[0]), "r"(a[1]), "r"(a[2]), "r"(a[3]), "r"(b[0]), "r"(b[1]));
}

static __device__ __forceinline__ void cp_async16(const __half* smem_dst, const __half* g) {
    uint32_t s = (uint32_t)__cvta_generic_to_shared(smem_dst);
    asm volatile("cp.async.cg.shared.global [%0], [%1], 16;\n" :: "r"(s), "l"(g));
}
static __device__ __forceinline__ void cp_commit() {
    asm volatile("cp.async.commit_group;\n");
}
template <int N>
static __device__ __forceinline__ void cp_wait() {
    asm volatile("cp.async.wait_group %0;\n" :: "n"(N));
}

// ---------------------------------------------------------------------------
// fp16 GEMM: C[M,N] = f(A @ B^T).  A [M,K] halves (row stride ldA), B [N,K]
// halves (row stride ldB). CTA tile TMx256 (TM in {64,128}), TILE_K=64.
//   TM=128: 8 warps as 2(M)x4(N), warp 64x64.   TM=64: 8 warps across N, 64x32.
// EPI=0: v = alpha*acc
// EPI=1: v = alpha*(acc + rowv[row] + colv[col])     (logits)
// EPI=2: v = acc + rowv[row]                         (vpT + wv fold)
// EPI=3: v = acc + bias[col]                         (attend final)
// OUT_HALF: C is __half (rn), else float.
// Optional second operand set (A2/B2) used for blockIdx.z >= zhalf (merged
// launches); C offset still uses the full z.
// ---------------------------------------------------------------------------
template <int TM, int EPI, bool OUT_HALF>
__global__ __launch_bounds__(256, 1)
void gemm_h(const __half* __restrict__ A, const __half* __restrict__ Bm,
            const float* __restrict__ rowv, const float* __restrict__ colv,
            const float* __restrict__ bias, void* __restrict__ Cv,
            int Ndim, int K, long long ldA, long long ldB, float alpha,
            long long sA, long long sB, long long sC,
            long long sRow, long long sCol,
            const __half* __restrict__ A2, const __half* __restrict__ B2,
            int zhalf)
{
    extern __shared__ __half smem[];

    constexpr int A_HALFS_T = TM * ROWH;
    constexpr int STAGE_HALFS_T = (TM + 256) * ROWH;
    constexpr int NJ = (TM == 128) ? 8 : 4;
    constexpr int ALOOP = TM / 32;

    const int z = blockIdx.z;
    const __half* Ab;
    const __half* Bb;
    if (z >= zhalf) {
        Ab = A2 + (long long)(z - zhalf) * sA;
        Bb = B2 + (long long)(z - zhalf) * sB;
    } else {
        Ab = A + (long long)z * sA;
        Bb = Bm + (long long)z * sB;
    }

    const int bm = blockIdx.y * TM;
    const int bn = blockIdx.x * 256;
    const int tid = threadIdx.x;
    const int lane = tid & 31;
    const int warp = tid >> 5;
    const int wm = (TM == 128) ? (warp & 1) * 64 : 0;
    const int wn = (TM == 128) ? (warp >> 1) * 64 : warp * 32;
    const int gr = lane >> 2;
    const int gc = lane & 3;

    float acc[4][NJ][4];
#pragma unroll
    for (int i = 0; i < 4; ++i)
#pragma unroll
        for (int j = 0; j < NJ; ++j)
#pragma unroll
            for (int r = 0; r < 4; ++r) acc[i][j][r] = 0.f;

    const int nk = K >> 6;

    auto load_tile = [&](int kt) {
        const int stage = kt & (STAGES - 1);
        __half* sAh = smem + stage * STAGE_HALFS_T;
        __half* sBh = sAh + A_HALFS_T;
        const int k0g = kt << 6;
#pragma unroll
        for (int i = 0; i < ALOOP; ++i) {
            const int ci = tid + i * 256;
            const int row = ci >> 3;
            const int ch = (ci & 7) * 8;
            cp_async16(sAh + row * ROWH + ch, Ab + (size_t)(bm + row) * ldA + k0g + ch);
        }
#pragma unroll
        for (int i = 0; i < 8; ++i) {
            const int ci = tid + i * 256;
            const int row = ci >> 3;
            const int ch = (ci & 7) * 8;
            cp_async16(sBh + row * ROWH + ch, Bb + (size_t)(bn + row) * ldB + k0g + ch);
        }
    };

#pragma unroll
    for (int s = 0; s < STAGES - 1; ++s) {
        load_tile(s);
        cp_commit();
    }

    for (int kt = 0; kt < nk; ++kt) {
        const int stage = kt & (STAGES - 1);
        cp_wait<STAGES - 2>();
        __syncthreads();

        const int pf = kt + STAGES - 1;
        if (pf < nk) load_tile(pf);
        cp_commit();

        const __half* sAh = smem + stage * STAGE_HALFS_T;
        const __half* sBh = sAh + A_HALFS_T;

#pragma unroll
        for (int k0 = 0; k0 < 64; k0 += 16) {
            uint32_t a[4][4];
#pragma unroll
            for (int i = 0; i < 4; ++i) {
                const int r = wm + i * 16 + gr;
                a[i][0] = *reinterpret_cast<const uint32_t*>(sAh + (size_t)r * ROWH + k0 + 2 * gc);
                a[i][1] = *reinterpret_cast<const uint32_t*>(sAh + (size_t)(r + 8) * ROWH + k0 + 2 * gc);
                a[i][2] = *reinterpret_cast<const uint32_t*>(sAh + (size_t)r * ROWH + k0 + 2 * gc + 8);
                a[i][3] = *reinterpret_cast<const uint32_t*>(sAh + (size_t)(r + 8) * ROWH + k0 + 2 * gc + 8);
            }
            uint32_t b[NJ][2];
#pragma unroll
            for (int j = 0; j < NJ; ++j) {
                const int cn = wn + j * 8 + gr;
                b[j][0] = *reinterpret_cast<const uint32_t*>(sBh + (size_t)cn * ROWH + k0 + 2 * gc);
                b[j][1] = *reinterpret_cast<const uint32_t*>(sBh + (size_t)cn * ROWH + k0 + 2 * gc + 8);
            }
#pragma unroll
            for (int i = 0; i < 4; ++i)
#pragma unroll
                for (int j = 0; j < NJ; ++j) mma_f16(acc[i][j], a[i], b[j]);
        }
        __syncthreads();
    }

    const float* rv = (EPI == 1 || EPI == 2) ? rowv + (long long)z * sRow : nullptr;
    const float* cv = (EPI == 1) ? colv + (long long)z * sCol : nullptr;

    float* Cf = (float*)Cv + (long long)z * sC;
    __half* Ch = (__half*)Cv + (long long)z * sC;

#pragma unroll
    for (int i = 0; i < 4; ++i) {
#pragma unroll
        for (int j = 0; j < NJ; ++j) {
            const int row = bm + wm + i * 16 + gr;
            const int col = bn + wn + j * 8 + gc * 2;
            float v0 = acc[i][j][0], v1 = acc[i][j][1];
            float v2 = acc[i][j][2], v3 = acc[i][j][3];
            if (EPI == 0) {
                v0 *= alpha; v1 *= alpha; v2 *= alpha; v3 *= alpha;
            } else if (EPI == 1) {
                const float u0 = rv[row], u8 = rv[row + 8];
                const float w0 = cv[col], w1 = cv[col + 1];
                v0 = (v0 + u0 + w0) * alpha;
                v1 = (v1 + u0 + w1) * alpha;
                v2 = (v2 + u8 + w0) * alpha;
                v3 = (v3 + u8 + w1) * alpha;
            } else if (EPI == 2) {
                const float r0 = rv[row], r8 = rv[row + 8];
                v0 += r0; v1 += r0; v2 += r8; v3 += r8;
            } else {
                const float b0 = bias[col], b1 = bias[col + 1];
                v0 += b0; v1 += b1; v2 += b0; v3 += b1;
            }
            if (OUT_HALF) {
                *reinterpret_cast<__half2*>(Ch + (size_t)row * Ndim + col) =
                    __floats2half2_rn(v0, v1);
                *reinterpret_cast<__half2*>(Ch + (size_t)(row + 8) * Ndim + col) =
                    __floats2half2_rn(v2, v3);
            } else {
                Cf[(size_t)row * Ndim + col] = v0;
                Cf[(size_t)row * Ndim + col + 1] = v1;
                Cf[(size_t)(row + 8) * Ndim + col] = v2;
                Cf[(size_t)(row + 8) * Ndim + col + 1] = v3;
            }
        }
    }
}

// float -> half copy, 4 tensors per launch (grid.y selects; per-y element count).
__global__ void copy_f2h4(const float4* __restrict__ i0, __half* __restrict__ o0,
                          const float4* __restrict__ i1, __half* __restrict__ o1,
                          const float4* __restrict__ i2, __half* __restrict__ o2,
                          const float4* __restrict__ i3, __half* __restrict__ o3,
                          int n4_abc, int n4_d)
{
    const int i = blockIdx.x * 256 + threadIdx.x;
    const int y = blockIdx.y;
    const int n4 = (y < 3) ? n4_abc : n4_d;
    if (i >= n4) return;
    const float4* in = (y == 0) ? i0 : (y == 1) ? i1 : (y == 2) ? i2 : i3;
    __half* out = (y == 0) ? o0 : (y == 1) ? o1 : (y == 2) ? o2 : o3;
    const float4 v = in[i];
    const __half2 h01 = __floats2half2_rn(v.x, v.y);
    const __half2 h23 = __floats2half2_rn(v.z, v.w);
    uint2 pk;
    pk.x = *reinterpret_cast<const uint32_t*>(&h01);
    pk.y = *reinterpret_cast<const uint32_t*>(&h23);
    *reinterpret_cast<uint2*>(out + (size_t)i * 4) = pk;
}

// Fused 32x32 tiled transposes (float in -> half out), grid.z selects tensor.
__global__ void transpose32h3(const float* __restrict__ in0, __half* __restrict__ out0,
                              const float* __restrict__ in1, __half* __restrict__ out1,
                              const float* __restrict__ in2, __half* __restrict__ out2,
                              int R, int Cc)
{
    __shared__ float sm[32][33];
    const float* in = (blockIdx.z == 0) ? in0 : (blockIdx.z == 1) ? in1 : in2;
    __half* outT = (blockIdx.z == 0) ? out0 : (blockIdx.z == 1) ? out1 : out2;
    const int r0 = blockIdx.x * 32;
    const int c0 = blockIdx.y * 32;
    const int tx = threadIdx.x, ty = threadIdx.y;
#pragma unroll
    for (int q = 0; q < 4; ++q)
        sm[ty + q * 8][tx] = in[(size_t)(r0 + ty + q * 8) * Cc + c0 + tx];
    __syncthreads();
#pragma unroll
    for (int q = 0; q < 4; ++q)
        outT[(size_t)(c0 + ty + q * 8) * R + r0 + tx] = __float2half_rn(sm[tx][ty + q * 8]);
}

// Sum NSPLIT partials (deterministic), emit half. grid.y: 0 -> out1, 1 -> out2
// (second bank of NSPLIT partials).
__global__ void reduce_splits_h2(const float4* __restrict__ part,
                                 __half* __restrict__ out1, __half* __restrict__ out2,
                                 int n4)
{
    const int i = blockIdx.x * blockDim.x + threadIdx.x;
    if (i >= n4) return;
    const float4* p = part + (size_t)blockIdx.y * NSPLIT * n4;
    float4 s = p[i];
#pragma unroll
    for (int q = 1; q < NSPLIT; ++q) {
        const float4 v = p[(size_t)q * n4 + i];
        s.x += v.x; s.y += v.y; s.z += v.z; s.w += v.w;
    }
    const __half2 h01 = __floats2half2_rn(s.x, s.y);
    const __half2 h23 = __floats2half2_rn(s.z, s.w);
    uint2 pk;
    pk.x = *reinterpret_cast<const uint32_t*>(&h01);
    pk.y = *reinterpret_cast<const uint32_t*>(&h23);
    __half* out = blockIdx.y ? out2 : out1;
    *reinterpret_cast<uint2*>(out + (size_t)i * 4) = pk;
}

// Batch-axis softmax, in place on fp16 logits, flat elementwise (no rowsum).
__global__ __launch_bounds__(256)
void softmax_b(__half* __restrict__ d)
{
    const int i = blockIdx.x * 256 + threadIdx.x;   // uint2 index within plane
    const size_t plane4 = (size_t)T_SZ * T_SZ / 4;
    uint2* p = reinterpret_cast<uint2*>(d);

    float4 v[B_SZ];
    float4 m = make_float4(-1e30f, -1e30f, -1e30f, -1e30f);
#pragma unroll
    for (int b = 0; b < B_SZ; ++b) {
        const uint2 pk = p[(size_t)b * plane4 + i];
        const __half2 h01 = *reinterpret_cast<const __half2*>(&pk.x);
        const __half2 h23 = *reinterpret_cast<const __half2*>(&pk.y);
        v[b].x = __half2float(__low2half(h01));
        v[b].y = __half2float(__high2half(h01));
        v[b].z = __half2float(__low2half(h23));
        v[b].w = __half2float(__high2half(h23));
        m.x = fmaxf(m.x, v[b].x); m.y = fmaxf(m.y, v[b].y);
        m.z = fmaxf(m.z, v[b].z); m.w = fmaxf(m.w, v[b].w);
    }
    float4 s = make_float4(0.f, 0.f, 0.f, 0.f);
#pragma unroll
    for (int b = 0; b < B_SZ; ++b) {
        v[b].x = __expf(v[b].x - m.x); s.x += v[b].x;
        v[b].y = __expf(v[b].y - m.y); s.y += v[b].y;
        v[b].z = __expf(v[b].z - m.z); s.z += v[b].z;
        v[b].w = __expf(v[b].w - m.w); s.w += v[b].w;
    }
    s.x = 1.f / s.x; s.y = 1.f / s.y; s.z = 1.f / s.z; s.w = 1.f / s.w;
#pragma unroll
    for (int b = 0; b < B_SZ; ++b) {
        const __half2 h01 = __floats2half2_rn(v[b].x * s.x, v[b].y * s.y);
        const __half2 h23 = __floats2half2_rn(v[b].z * s.z, v[b].w * s.w);
        uint2 pk;
        pk.x = *reinterpret_cast<const uint32_t*>(&h01);
        pk.y = *reinterpret_cast<const uint32_t*>(&h23);
        p[(size_t)b * plane4 + i] = pk;
    }
}

// colvec stage 1 (both weights, grid z in {0,1}).
__global__ void colvec_part(const float* __restrict__ W1, const float* __restrict__ b1,
                            const float* __restrict__ W2, const float* __restrict__ b2,
                            float* __restrict__ part)
{
    const float* W = blockIdx.z ? W2 : W1;
    const float* b = blockIdx.z ? b2 : b1;
    const int e = blockIdx.x * 128 + threadIdx.x;
    const int ch = blockIdx.y;
    const int h0 = ch * (HE_SZ / NCH);
    float s0 = 0.f, s1 = 0.f;
#pragma unroll
    for (int h = h0; h < h0 + HE_SZ / NCH; h += 2) {
        s0 += W[(size_t)h * E_SZ + e] * b[h];
        s1 += W[(size_t)(h + 1) * E_SZ + e] * b[h + 1];
    }
    part[((size_t)blockIdx.z * NCH + ch) * E_SZ + e] = s0 + s1;
}
__global__ void colvec_red(const float* __restrict__ part,
                           float* __restrict__ out1, float* __restrict__ out2)
{
    const int e = blockIdx.x * 128 + threadIdx.x;
    const size_t zb = (size_t)blockIdx.y * NCH * E_SZ;
    float s = 0.f;
#pragma unroll
    for (int ch = 0; ch < NCH; ++ch) s += part[zb + (size_t)ch * E_SZ + e];
    (blockIdx.y ? out2 : out1)[e] = s;
}

// wv[e] = Wo[e,:] . bv
__global__ void rowvec(const float* __restrict__ Wo, const float* __restrict__ bv,
                       float* __restrict__ out)
{
    __shared__ float red[256];
    const int e = blockIdx.x;
    const int t = threadIdx.x;
    const float4* r = reinterpret_cast<const float4*>(Wo + (size_t)e * HE_SZ);
    const float4* b4 = reinterpret_cast<const float4*>(bv);
    float s = 0.f;
#pragma unroll
    for (int i = 0; i < 4; ++i) {
        const float4 a = r[t + i * 256];
        const float4 b = b4[t + i * 256];
        s += a.x * b.x + a.y * b.y + a.z * b.z + a.w * b.w;
    }
    red[t] = s;
    __syncthreads();
    for (int o = 128; o; o >>= 1) {
        if (t < o) red[t] += red[t + o];
        __syncthreads();
    }
    if (t == 0) out[e] = red[0];
}

__global__ void dotscalar(const float* __restrict__ a, const float* __restrict__ b,
                          float* __restrict__ out)
{
    __shared__ float red[256];
    float s = 0.f;
    for (int i = threadIdx.x; i < HE_SZ; i += 256) s += a[i] * b[i];
    red[threadIdx.x] = s;
    __syncthreads();
    for (int o = 128; o; o >>= 1) {
        if (threadIdx.x < o) red[threadIdx.x] += red[threadIdx.x + o];
        __syncthreads();
    }
    if (threadIdx.x == 0) out[0] = red[0];
}

// Fused u/w: y=0: u[r] = query[r,:].a1 ; y=1: w[r] = key[r,:].a2 + c
__global__ void dotvec2(const float* __restrict__ query, const float* __restrict__ key,
                        const float* __restrict__ a1, const float* __restrict__ a2,
                        const float* __restrict__ cptr,
                        float* __restrict__ u, float* __restrict__ w)
{
    const int wid = threadIdx.x >> 5;
    const int lane = threadIdx.x & 31;
    const int r = blockIdx.x * 8 + wid;
    const bool isw = blockIdx.y != 0;
    const float* in = isw ? key : query;
    const float* vec = isw ? a2 : a1;
    const float4* p = reinterpret_cast<const float4*>(in + (size_t)r * E_SZ);
    const float4* v4 = reinterpret_cast<const float4*>(vec);
    float s = 0.f;
#pragma unroll
    for (int i = 0; i < 4; ++i) {
        const float4 a = p[lane + i * 32];
        const float4 b = v4[lane + i * 32];
        s += a.x * b.x + a.y * b.y + a.z * b.z + a.w * b.w;
    }
#pragma unroll
    for (int o = 16; o; o >>= 1) s += __shfl_xor_sync(0xffffffffu, s, o);
    if (lane == 0) {
        if (isw) w[r] = s + cptr[0];
        else u[r] = s;
    }
}

extern "C" void kernel_launch(void* const* d_in, const int* in_sizes, int n_in,
                              void* d_out, int out_size)
{
    (void)in_sizes; (void)n_in; (void)out_size;
    const float* key   = (const float*)d_in[0];
    const float* value = (const float*)d_in[1];
    const float* query = (const float*)d_in[2];
    const float* Wk = (const float*)d_in[3];
    const float* bk = (const float*)d_in[4];
    const float* Wv = (const float*)d_in[5];
    const float* bv = (const float*)d_in[6];
    const float* Wq = (const float*)d_in[7];
    const float* bq = (const float*)d_in[8];
    const float* Wo = (const float*)d_in[9];
    const float* bo = (const float*)d_in[10];
    float* out = (float*)d_out;

    float *part, *cpart, *a1, *a2, *wv, *cs, *u, *w;
    __half *atth, *qh, *kh, *vh, *Woh, *WqT, *WkT, *WvT, *MTh, *Ph, *qMh, *vpTh;
    cudaGetSymbolAddress((void**)&atth, g_atth);
    cudaGetSymbolAddress((void**)&qh, g_qh);
    cudaGetSymbolAddress((void**)&kh, g_kh);
    cudaGetSymbolAddress((void**)&vh, g_vh);
    cudaGetSymbolAddress((void**)&Woh, g_Woh);
    cudaGetSymbolAddress((void**)&WqT, g_WqT);
    cudaGetSymbolAddress((void**)&WkT, g_WkT);
    cudaGetSymbolAddress((void**)&WvT, g_WvT);
    cudaGetSymbolAddress((void**)&MTh, g_MTh);
    cudaGetSymbolAddress((void**)&Ph, g_Ph);
    cudaGetSymbolAddress((void**)&qMh, g_qMh);
    cudaGetSymbolAddress((void**)&vpTh, g_vpTh);
    cudaGetSymbolAddress((void**)&part, g_part);
    cudaGetSymbolAddress((void**)&cpart, g_cpart);
    cudaGetSymbolAddress((void**)&a1, g_a1);
    cudaGetSymbolAddress((void**)&a2, g_a2);
    cudaGetSymbolAddress((void**)&wv, g_wv);
    cudaGetSymbolAddress((void**)&cs, g_c);
    cudaGetSymbolAddress((void**)&u, g_u);
    cudaGetSymbolAddress((void**)&w, g_w);

    cudaFuncSetAttribute((const void*)gemm_h<128, 0, false>,
                         cudaFuncAttributeMaxDynamicSharedMemorySize, GSMEM_128);
    cudaFuncSetAttribute((const void*)gemm_h<128, 1, true>,
                         cudaFuncAttributeMaxDynamicSharedMemorySize, GSMEM_128);
    cudaFuncSetAttribute((const void*)gemm_h<64, 0, true>,
                         cudaFuncAttributeMaxDynamicSharedMemorySize, GSMEM_64);
    cudaFuncSetAttribute((const void*)gemm_h<64, 2, true>,
                         cudaFuncAttributeMaxDynamicSharedMemorySize, GSMEM_64);
    cudaFuncSetAttribute((const void*)gemm_h<64, 3, false>,
                         cudaFuncAttributeMaxDynamicSharedMemorySize, GSMEM_64);

    const int MT_ROWS = B_SZ * T_SZ;  // 16384
    const dim3 blk(256);
    const long long sTE = (long long)T_SZ * E_SZ;
    const long long sTT = (long long)T_SZ * T_SZ;
    const long long sET = (long long)E_SZ * T_SZ;
    const long long sEE = (long long)E_SZ * E_SZ;
    const int KC = HE_SZ / NSPLIT;  // 512

    // --- pre-pass ---
    {
        const int nin4 = MT_ROWS * E_SZ / 4;
        const int nw4 = E_SZ * HE_SZ / 4;
        copy_f2h4<<<dim3((nin4 + 255) / 256, 4), 256>>>(
            (const float4*)query, qh, (const float4*)key, kh,
            (const float4*)value, vh, (const float4*)Wo, Woh, nin4, nw4);
        transpose32h3<<<dim3(HE_SZ / 32, E_SZ / 32, 3), dim3(32, 8)>>>(
            Wq, WqT, Wk, WkT, Wv, WvT, HE_SZ, E_SZ);
        colvec_part<<<dim3(E_SZ / 128, NCH, 2), 128>>>(Wq, bk, Wk, bq, cpart);
        colvec_red<<<dim3(E_SZ / 128, 2), 128>>>(cpart, a1, a2);
        rowvec<<<E_SZ, 256>>>(Wo, bv, wv);
        dotscalar<<<1, 256>>>(bq, bk, cs);
        dotvec2<<<dim3(MT_ROWS / 8, 2), 256>>>(query, key, a1, a2, cs, u, w);
    }

    // Merged split-K launch: z<8 -> M^T = WkT@WqT^T chunks; z>=8 -> P = Woh@WvT^T.
    gemm_h<128, 0, false><<<dim3(E_SZ / 256, E_SZ / 128, 2 * NSPLIT), blk, GSMEM_128>>>(
        WkT, WqT, nullptr, nullptr, nullptr, part, E_SZ, KC, HE_SZ, HE_SZ, 1.f,
        KC, KC, sEE, 0, 0, Woh, WvT, NSPLIT);
    reduce_splits_h2<<<dim3((E_SZ * E_SZ / 4 + 255) / 256, 2), 256>>>(
        (float4*)part, MTh, Ph, E_SZ * E_SZ / 4);

    // qM = qh @ MTh^T   [16384,512] (half out), TM=64 -> 512 CTAs
    gemm_h<64, 0, true><<<dim3(E_SZ / 256, MT_ROWS / 64, 1), blk, GSMEM_64>>>(
        qh, MTh, nullptr, nullptr, nullptr, qMh, E_SZ, E_SZ, E_SZ, E_SZ, 1.f,
        0, 0, 0, 0, 0, nullptr, nullptr, 9999);
    // vpT' = Ph @ vh^T + wv[row], per batch [512,2048] (half out), TM=64
    gemm_h<64, 2, true><<<dim3(T_SZ / 256, E_SZ / 64, B_SZ), blk, GSMEM_64>>>(
        Ph, vh, wv, nullptr, nullptr, vpTh, T_SZ, E_SZ, E_SZ, E_SZ, 1.f,
        0, sTE, sET, 0, 0, nullptr, nullptr, 9999);
    // logits: atth = h( SCALE*(qMh @ kh^T + u + w) ) per batch (half out)
    gemm_h<128, 1, true><<<dim3(T_SZ / 256, T_SZ / 128, B_SZ), blk, GSMEM_128>>>(
        qMh, kh, u, w, nullptr, atth, T_SZ, E_SZ, E_SZ, E_SZ, SCALE_F,
        sTE, sTE, sTT, T_SZ, T_SZ, nullptr, nullptr, 9999);
    // batch-axis softmax in place (flat; no rowsum needed anymore)
    softmax_b<<<(T_SZ * T_SZ / 4) / 256, 256>>>(atth);
    // out = atth @ vpT'^T + bo per batch (float out), TM=64 -> 512 CTAs
    gemm_h<64, 3, false><<<dim3(E_SZ / 256, T_SZ / 64, B_SZ), blk, GSMEM_64>>>(
        atth, vpTh, nullptr, nullptr, bo, out, E_SZ, T_SZ, T_SZ, T_SZ, 1.f,
        sTT, sET, sTE, 0, 0, nullptr, nullptr, 9999);
}

// round 16
// speedup vs baseline: 1.1228x; 1.1228x over previous
#include <cuda_runtime.h>
#include <cuda_fp16.h>
#include <cstdint>
#include <cstddef>

// ---------------------------------------------------------------------------
// MultiheadedAttention2 (batch-axis softmax) — v16: fp16 mma.sync GEMMs.
//   att = softmax_b( SCALE*(qM@key^T + u + w) ),  qM = query@M, M = Wq^T Wk
//   out = att@vpT'^T + bo,   vpT'[e][s] = (P@value^T)[e][s] + wv[e]
// v15's wv-fold + flat softmax + merged M&P launch, with R12's proven
// TM=128 tiles everywhere (TM=64 doubled B re-reads and regressed).
// fp16 operands / fp32 accum; u/w/c/bo exact fp32.
// ---------------------------------------------------------------------------

#define B_SZ 8
#define T_SZ 2048
#define E_SZ 512
#define HE_SZ 4096
#define SCALE_F 0.04419417382415922f  // 512^-0.5

#define STAGES 4
#define ROWH 72                         // padded row: 72 halves = 144 B
#define A_HALFS (128 * ROWH)            // 9216
#define B_HALFS (256 * ROWH)            // 18432
#define STAGE_HALFS (A_HALFS + B_HALFS) // 27648
#define GSMEM_BYTES (STAGES * STAGE_HALFS * 2)  // 221184
#define NSPLIT 8
#define NCH 64

// Scratch (device globals; allocation-free rule)
__device__ __half g_atth[(size_t)B_SZ * T_SZ * T_SZ];   // logits -> att (fp16)
__device__ __half g_qh[(size_t)B_SZ * T_SZ * E_SZ];
__device__ __half g_kh[(size_t)B_SZ * T_SZ * E_SZ];
__device__ __half g_vh[(size_t)B_SZ * T_SZ * E_SZ];
__device__ __half g_Woh[(size_t)E_SZ * HE_SZ];
__device__ __half g_WqT[(size_t)E_SZ * HE_SZ];
__device__ __half g_WkT[(size_t)E_SZ * HE_SZ];
__device__ __half g_WvT[(size_t)E_SZ * HE_SZ];
__device__ __half g_MTh[(size_t)E_SZ * E_SZ];
__device__ __half g_Ph[(size_t)E_SZ * E_SZ];
__device__ __half g_qMh[(size_t)B_SZ * T_SZ * E_SZ];
__device__ __half g_vpTh[(size_t)B_SZ * E_SZ * T_SZ];
__device__ float  g_part[(size_t)2 * NSPLIT * E_SZ * E_SZ];
__device__ float  g_cpart[(size_t)2 * NCH * E_SZ];
__device__ float  g_a1[E_SZ];
__device__ float  g_a2[E_SZ];
__device__ float  g_wv[E_SZ];
__device__ float  g_c[1];
__device__ float  g_u[(size_t)B_SZ * T_SZ];
__device__ float  g_w[(size_t)B_SZ * T_SZ];

static __device__ __forceinline__ void mma_f16(float* c, const uint32_t* a, const uint32_t* b) {
    asm volatile(
        "mma.sync.aligned.m16n8k16.row.col.f32.f16.f16.f32 "
        "{%0,%1,%2,%3}, {%4,%5,%6,%7}, {%8,%9}, {%0,%1,%2,%3};\n"
        : "+f"(c[0]), "+f"(c[1]), "+f"(c[2]), "+f"(c[3])
        : "r"(a[0]), "r"(a[1]), "r"(a[2]), "r"(a[3]), "r"(b[0]), "r"(b[1]));
}

static __device__ __forceinline__ void cp_async16(const __half* smem_dst, const __half* g) {
    uint32_t s = (uint32_t)__cvta_generic_to_shared(smem_dst);
    asm volatile("cp.async.cg.shared.global [%0], [%1], 16;\n" :: "r"(s), "l"(g));
}
static __device__ __forceinline__ void cp_commit() {
    asm volatile("cp.async.commit_group;\n");
}
template <int N>
static __device__ __forceinline__ void cp_wait() {
    asm volatile("cp.async.wait_group %0;\n" :: "n"(N));
}

// ---------------------------------------------------------------------------
// fp16 GEMM: C[M,N] = f(A @ B^T).  A [M,K] halves (row stride ldA), B [N,K]
// halves (row stride ldB). CTA tile 128x256, warp tile 64x64, TILE_K=64.
// EPI=0: v = alpha*acc
// EPI=1: v = alpha*(acc + rowv[row] + colv[col])     (logits)
// EPI=2: v = acc + rowv[row]                         (vpT + wv fold)
// EPI=3: v = acc + bias[col]                         (attend final)
// OUT_HALF: C is __half (rn), else float.
// Optional second operand set (A2/B2) for blockIdx.z >= zhalf (merged launch).
// ---------------------------------------------------------------------------
template <int EPI, bool OUT_HALF>
__global__ __launch_bounds__(256, 1)
void gemm_h(const __half* __restrict__ A, const __half* __restrict__ Bm,
            const float* __restrict__ rowv, const float* __restrict__ colv,
            const float* __restrict__ bias, void* __restrict__ Cv,
            int Ndim, int K, long long ldA, long long ldB, float alpha,
            long long sA, long long sB, long long sC,
            long long sRow, long long sCol,
            const __half* __restrict__ A2, const __half* __restrict__ B2,
            int zhalf)
{
    extern __shared__ __half smem[];

    const int z = blockIdx.z;
    const __half* Ab;
    const __half* Bb;
    if (z >= zhalf) {
        Ab = A2 + (long long)(z - zhalf) * sA;
        Bb = B2 + (long long)(z - zhalf) * sB;
    } else {
        Ab = A + (long long)z * sA;
        Bb = Bm + (long long)z * sB;
    }

    const int bm = blockIdx.y * 128;
    const int bn = blockIdx.x * 256;
    const int tid = threadIdx.x;
    const int lane = tid & 31;
    const int warp = tid >> 5;          // 0..7
    const int wm = (warp & 1) * 64;     // 2 warps down M
    const int wn = (warp >> 1) * 64;    // 4 warps across N
    const int gr = lane >> 2;           // 0..7
    const int gc = lane & 3;            // 0..3

    float acc[4][8][4];
#pragma unroll
    for (int i = 0; i < 4; ++i)
#pragma unroll
        for (int j = 0; j < 8; ++j)
#pragma unroll
            for (int r = 0; r < 4; ++r) acc[i][j][r] = 0.f;

    const int nk = K >> 6;

    auto load_tile = [&](int kt) {
        const int stage = kt & (STAGES - 1);
        __half* sAh = smem + stage * STAGE_HALFS;
        __half* sBh = sAh + A_HALFS;
        const int k0g = kt << 6;
#pragma unroll
        for (int i = 0; i < 4; ++i) {
            const int ci = tid + i * 256;
            const int row = ci >> 3;
            const int ch = (ci & 7) * 8;
            cp_async16(sAh + row * ROWH + ch, Ab + (size_t)(bm + row) * ldA + k0g + ch);
        }
#pragma unroll
        for (int i = 0; i < 8; ++i) {
            const int ci = tid + i * 256;
            const int row = ci >> 3;
            const int ch = (ci & 7) * 8;
            cp_async16(sBh + row * ROWH + ch, Bb + (size_t)(bn + row) * ldB + k0g + ch);
        }
    };

#pragma unroll
    for (int s = 0; s < STAGES - 1; ++s) {
        load_tile(s);
        cp_commit();
    }

    for (int kt = 0; kt < nk; ++kt) {
        const int stage = kt & (STAGES - 1);
        cp_wait<STAGES - 2>();
        __syncthreads();

        const int pf = kt + STAGES - 1;
        if (pf < nk) load_tile(pf);
        cp_commit();

        const __half* sAh = smem + stage * STAGE_HALFS;
        const __half* sBh = sAh + A_HALFS;

#pragma unroll
        for (int k0 = 0; k0 < 64; k0 += 16) {
            uint32_t a[4][4];
#pragma unroll
            for (int i = 0; i < 4; ++i) {
                const int r = wm + i * 16 + gr;
                a[i][0] = *reinterpret_cast<const uint32_t*>(sAh + (size_t)r * ROWH + k0 + 2 * gc);
                a[i][1] = *reinterpret_cast<const uint32_t*>(sAh + (size_t)(r + 8) * ROWH + k0 + 2 * gc);
                a[i][2] = *reinterpret_cast<const uint32_t*>(sAh + (size_t)r * ROWH + k0 + 2 * gc + 8);
                a[i][3] = *reinterpret_cast<const uint32_t*>(sAh + (size_t)(r + 8) * ROWH + k0 + 2 * gc + 8);
            }
            uint32_t b[8][2];
#pragma unroll
            for (int j = 0; j < 8; ++j) {
                const int cn = wn + j * 8 + gr;
                b[j][0] = *reinterpret_cast<const uint32_t*>(sBh + (size_t)cn * ROWH + k0 + 2 * gc);
                b[j][1] = *reinterpret_cast<const uint32_t*>(sBh + (size_t)cn * ROWH + k0 + 2 * gc + 8);
            }
#pragma unroll
            for (int i = 0; i < 4; ++i)
#pragma unroll
                for (int j = 0; j < 8; ++j) mma_f16(acc[i][j], a[i], b[j]);
        }
        __syncthreads();
    }

    const float* rv = (EPI == 1 || EPI == 2) ? rowv + (long long)z * sRow : nullptr;
    const float* cv = (EPI == 1) ? colv + (long long)z * sCol : nullptr;

    float* Cf = (float*)Cv + (long long)z * sC;
    __half* Ch = (__half*)Cv + (long long)z * sC;

#pragma unroll
    for (int i = 0; i < 4; ++i) {
#pragma unroll
        for (int j = 0; j < 8; ++j) {
            const int row = bm + wm + i * 16 + gr;
            const int col = bn + wn + j * 8 + gc * 2;
            float v0 = acc[i][j][0], v1 = acc[i][j][1];
            float v2 = acc[i][j][2], v3 = acc[i][j][3];
            if (EPI == 0) {
                v0 *= alpha; v1 *= alpha; v2 *= alpha; v3 *= alpha;
            } else if (EPI == 1) {
                const float u0 = rv[row], u8 = rv[row + 8];
                const float w0 = cv[col], w1 = cv[col + 1];
                v0 = (v0 + u0 + w0) * alpha;
                v1 = (v1 + u0 + w1) * alpha;
                v2 = (v2 + u8 + w0) * alpha;
                v3 = (v3 + u8 + w1) * alpha;
            } else if (EPI == 2) {
                const float r0 = rv[row], r8 = rv[row + 8];
                v0 += r0; v1 += r0; v2 += r8; v3 += r8;
            } else {
                const float b0 = bias[col], b1 = bias[col + 1];
                v0 += b0; v1 += b1; v2 += b0; v3 += b1;
            }
            if (OUT_HALF) {
                *reinterpret_cast<__half2*>(Ch + (size_t)row * Ndim + col) =
                    __floats2half2_rn(v0, v1);
                *reinterpret_cast<__half2*>(Ch + (size_t)(row + 8) * Ndim + col) =
                    __floats2half2_rn(v2, v3);
            } else {
                Cf[(size_t)row * Ndim + col] = v0;
                Cf[(size_t)row * Ndim + col + 1] = v1;
                Cf[(size_t)(row + 8) * Ndim + col] = v2;
                Cf[(size_t)(row + 8) * Ndim + col + 1] = v3;
            }
        }
    }
}

// float -> half copy, 4 tensors per launch (grid.y selects; per-y element count).
__global__ void copy_f2h4(const float4* __restrict__ i0, __half* __restrict__ o0,
                          const float4* __restrict__ i1, __half* __restrict__ o1,
                          const float4* __restrict__ i2, __half* __restrict__ o2,
                          const float4* __restrict__ i3, __half* __restrict__ o3,
                          int n4_abc, int n4_d)
{
    const int i = blockIdx.x * 256 + threadIdx.x;
    const int y = blockIdx.y;
    const int n4 = (y < 3) ? n4_abc : n4_d;
    if (i >= n4) return;
    const float4* in = (y == 0) ? i0 : (y == 1) ? i1 : (y == 2) ? i2 : i3;
    __half* out = (y == 0) ? o0 : (y == 1) ? o1 : (y == 2) ? o2 : o3;
    const float4 v = in[i];
    const __half2 h01 = __floats2half2_rn(v.x, v.y);
    const __half2 h23 = __floats2half2_rn(v.z, v.w);
    uint2 pk;
    pk.x = *reinterpret_cast<const uint32_t*>(&h01);
    pk.y = *reinterpret_cast<const uint32_t*>(&h23);
    *reinterpret_cast<uint2*>(out + (size_t)i * 4) = pk;
}

// Fused 32x32 tiled transposes (float in -> half out), grid.z selects tensor.
__global__ void transpose32h3(const float* __restrict__ in0, __half* __restrict__ out0,
                              const float* __restrict__ in1, __half* __restrict__ out1,
                              const float* __restrict__ in2, __half* __restrict__ out2,
                              int R, int Cc)
{
    __shared__ float sm[32][33];
    const float* in = (blockIdx.z == 0) ? in0 : (blockIdx.z == 1) ? in1 : in2;
    __half* outT = (blockIdx.z == 0) ? out0 : (blockIdx.z == 1) ? out1 : out2;
    const int r0 = blockIdx.x * 32;
    const int c0 = blockIdx.y * 32;
    const int tx = threadIdx.x, ty = threadIdx.y;
#pragma unroll
    for (int q = 0; q < 4; ++q)
        sm[ty + q * 8][tx] = in[(size_t)(r0 + ty + q * 8) * Cc + c0 + tx];
    __syncthreads();
#pragma unroll
    for (int q = 0; q < 4; ++q)
        outT[(size_t)(c0 + ty + q * 8) * R + r0 + tx] = __float2half_rn(sm[tx][ty + q * 8]);
}

// Sum NSPLIT partials (deterministic), emit half. grid.y selects bank/output.
__global__ void reduce_splits_h2(const float4* __restrict__ part,
                                 __half* __restrict__ out1, __half* __restrict__ out2,
                                 int n4)
{
    const int i = blockIdx.x * blockDim.x + threadIdx.x;
    if (i >= n4) return;
    const float4* p = part + (size_t)blockIdx.y * NSPLIT * n4;
    float4 s = p[i];
#pragma unroll
    for (int q = 1; q < NSPLIT; ++q) {
        const float4 v = p[(size_t)q * n4 + i];
        s.x += v.x; s.y += v.y; s.z += v.z; s.w += v.w;
    }
    const __half2 h01 = __floats2half2_rn(s.x, s.y);
    const __half2 h23 = __floats2half2_rn(s.z, s.w);
    uint2 pk;
    pk.x = *reinterpret_cast<const uint32_t*>(&h01);
    pk.y = *reinterpret_cast<const uint32_t*>(&h23);
    __half* out = blockIdx.y ? out2 : out1;
    *reinterpret_cast<uint2*>(out + (size_t)i * 4) = pk;
}

// Batch-axis softmax, in place on fp16 logits, flat elementwise (no rowsum).
__global__ __launch_bounds__(256)
void softmax_b(__half* __restrict__ d)
{
    const int i = blockIdx.x * 256 + threadIdx.x;   // uint2 index within plane
    const size_t plane4 = (size_t)T_SZ * T_SZ / 4;
    uint2* p = reinterpret_cast<uint2*>(d);

    float4 v[B_SZ];
    float4 m = make_float4(-1e30f, -1e30f, -1e30f, -1e30f);
#pragma unroll
    for (int b = 0; b < B_SZ; ++b) {
        const uint2 pk = p[(size_t)b * plane4 + i];
        const __half2 h01 = *reinterpret_cast<const __half2*>(&pk.x);
        const __half2 h23 = *reinterpret_cast<const __half2*>(&pk.y);
        v[b].x = __half2float(__low2half(h01));
        v[b].y = __half2float(__high2half(h01));
        v[b].z = __half2float(__low2half(h23));
        v[b].w = __half2float(__high2half(h23));
        m.x = fmaxf(m.x, v[b].x); m.y = fmaxf(m.y, v[b].y);
        m.z = fmaxf(m.z, v[b].z); m.w = fmaxf(m.w, v[b].w);
    }
    float4 s = make_float4(0.f, 0.f, 0.f, 0.f);
#pragma unroll
    for (int b = 0; b < B_SZ; ++b) {
        v[b].x = __expf(v[b].x - m.x); s.x += v[b].x;
        v[b].y = __expf(v[b].y - m.y); s.y += v[b].y;
        v[b].z = __expf(v[b].z - m.z); s.z += v[b].z;
        v[b].w = __expf(v[b].w - m.w); s.w += v[b].w;
    }
    s.x = 1.f / s.x; s.y = 1.f / s.y; s.z = 1.f / s.z; s.w = 1.f / s.w;
#pragma unroll
    for (int b = 0; b < B_SZ; ++b) {
        const __half2 h01 = __floats2half2_rn(v[b].x * s.x, v[b].y * s.y);
        const __half2 h23 = __floats2half2_rn(v[b].z * s.z, v[b].w * s.w);
        uint2 pk;
        pk.x = *reinterpret_cast<const uint32_t*>(&h01);
        pk.y = *reinterpret_cast<const uint32_t*>(&h23);
        p[(size_t)b * plane4 + i] = pk;
    }
}

// colvec stage 1 (both weights, grid z in {0,1}).
__global__ void colvec_part(const float* __restrict__ W1, const float* __restrict__ b1,
                            const float* __restrict__ W2, const float* __restrict__ b2,
                            float* __restrict__ part)
{
    const float* W = blockIdx.z ? W2 : W1;
    const float* b = blockIdx.z ? b2 : b1;
    const int e = blockIdx.x * 128 + threadIdx.x;
    const int ch = blockIdx.y;
    const int h0 = ch * (HE_SZ / NCH);
    float s0 = 0.f, s1 = 0.f;
#pragma unroll
    for (int h = h0; h < h0 + HE_SZ / NCH; h += 2) {
        s0 += W[(size_t)h * E_SZ + e] * b[h];
        s1 += W[(size_t)(h + 1) * E_SZ + e] * b[h + 1];
    }
    part[((size_t)blockIdx.z * NCH + ch) * E_SZ + e] = s0 + s1;
}
__global__ void colvec_red(const float* __restrict__ part,
                           float* __restrict__ out1, float* __restrict__ out2)
{
    const int e = blockIdx.x * 128 + threadIdx.x;
    const size_t zb = (size_t)blockIdx.y * NCH * E_SZ;
    float s = 0.f;
#pragma unroll
    for (int ch = 0; ch < NCH; ++ch) s += part[zb + (size_t)ch * E_SZ + e];
    (blockIdx.y ? out2 : out1)[e] = s;
}

// wv[e] = Wo[e,:] . bv
__global__ void rowvec(const float* __restrict__ Wo, const float* __restrict__ bv,
                       float* __restrict__ out)
{
    __shared__ float red[256];
    const int e = blockIdx.x;
    const int t = threadIdx.x;
    const float4* r = reinterpret_cast<const float4*>(Wo + (size_t)e * HE_SZ);
    const float4* b4 = reinterpret_cast<const float4*>(bv);
    float s = 0.f;
#pragma unroll
    for (int i = 0; i < 4; ++i) {
        const float4 a = r[t + i * 256];
        const float4 b = b4[t + i * 256];
        s += a.x * b.x + a.y * b.y + a.z * b.z + a.w * b.w;
    }
    red[t] = s;
    __syncthreads();
    for (int o = 128; o; o >>= 1) {
        if (t < o) red[t] += red[t + o];
        __syncthreads();
    }
    if (t == 0) out[e] = red[0];
}

__global__ void dotscalar(const float* __restrict__ a, const float* __restrict__ b,
                          float* __restrict__ out)
{
    __shared__ float red[256];
    float s = 0.f;
    for (int i = threadIdx.x; i < HE_SZ; i += 256) s += a[i] * b[i];
    red[threadIdx.x] = s;
    __syncthreads();
    for (int o = 128; o; o >>= 1) {
        if (threadIdx.x < o) red[threadIdx.x] += red[threadIdx.x + o];
        __syncthreads();
    }
    if (threadIdx.x == 0) out[0] = red[0];
}

// Fused u/w: y=0: u[r] = query[r,:].a1 ; y=1: w[r] = key[r,:].a2 + c
__global__ void dotvec2(const float* __restrict__ query, const float* __restrict__ key,
                        const float* __restrict__ a1, const float* __restrict__ a2,
                        const float* __restrict__ cptr,
                        float* __restrict__ u, float* __restrict__ w)
{
    const int wid = threadIdx.x >> 5;
    const int lane = threadIdx.x & 31;
    const int r = blockIdx.x * 8 + wid;
    const bool isw = blockIdx.y != 0;
    const float* in = isw ? key : query;
    const float* vec = isw ? a2 : a1;
    const float4* p = reinterpret_cast<const float4*>(in + (size_t)r * E_SZ);
    const float4* v4 = reinterpret_cast<const float4*>(vec);
    float s = 0.f;
#pragma unroll
    for (int i = 0; i < 4; ++i) {
        const float4 a = p[lane + i * 32];
        const float4 b = v4[lane + i * 32];
        s += a.x * b.x + a.y * b.y + a.z * b.z + a.w * b.w;
    }
#pragma unroll
    for (int o = 16; o; o >>= 1) s += __shfl_xor_sync(0xffffffffu, s, o);
    if (lane == 0) {
        if (isw) w[r] = s + cptr[0];
        else u[r] = s;
    }
}

extern "C" void kernel_launch(void* const* d_in, const int* in_sizes, int n_in,
                              void* d_out, int out_size)
{
    (void)in_sizes; (void)n_in; (void)out_size;
    const float* key   = (const float*)d_in[0];
    const float* value = (const float*)d_in[1];
    const float* query = (const float*)d_in[2];
    const float* Wk = (const float*)d_in[3];
    const float* bk = (const float*)d_in[4];
    const float* Wv = (const float*)d_in[5];
    const float* bv = (const float*)d_in[6];
    const float* Wq = (const float*)d_in[7];
    const float* bq = (const float*)d_in[8];
    const float* Wo = (const float*)d_in[9];
    const float* bo = (const float*)d_in[10];
    float* out = (float*)d_out;

    float *part, *cpart, *a1, *a2, *wv, *cs, *u, *w;
    __half *atth, *qh, *kh, *vh, *Woh, *WqT, *WkT, *WvT, *MTh, *Ph, *qMh, *vpTh;
    cudaGetSymbolAddress((void**)&atth, g_atth);
    cudaGetSymbolAddress((void**)&qh, g_qh);
    cudaGetSymbolAddress((void**)&kh, g_kh);
    cudaGetSymbolAddress((void**)&vh, g_vh);
    cudaGetSymbolAddress((void**)&Woh, g_Woh);
    cudaGetSymbolAddress((void**)&WqT, g_WqT);
    cudaGetSymbolAddress((void**)&WkT, g_WkT);
    cudaGetSymbolAddress((void**)&WvT, g_WvT);
    cudaGetSymbolAddress((void**)&MTh, g_MTh);
    cudaGetSymbolAddress((void**)&Ph, g_Ph);
    cudaGetSymbolAddress((void**)&qMh, g_qMh);
    cudaGetSymbolAddress((void**)&vpTh, g_vpTh);
    cudaGetSymbolAddress((void**)&part, g_part);
    cudaGetSymbolAddress((void**)&cpart, g_cpart);
    cudaGetSymbolAddress((void**)&a1, g_a1);
    cudaGetSymbolAddress((void**)&a2, g_a2);
    cudaGetSymbolAddress((void**)&wv, g_wv);
    cudaGetSymbolAddress((void**)&cs, g_c);
    cudaGetSymbolAddress((void**)&u, g_u);
    cudaGetSymbolAddress((void**)&w, g_w);

    cudaFuncSetAttribute((const void*)gemm_h<0, false>,
                         cudaFuncAttributeMaxDynamicSharedMemorySize, GSMEM_BYTES);
    cudaFuncSetAttribute((const void*)gemm_h<0, true>,
                         cudaFuncAttributeMaxDynamicSharedMemorySize, GSMEM_BYTES);
    cudaFuncSetAttribute((const void*)gemm_h<1, true>,
                         cudaFuncAttributeMaxDynamicSharedMemorySize, GSMEM_BYTES);
    cudaFuncSetAttribute((const void*)gemm_h<2, true>,
                         cudaFuncAttributeMaxDynamicSharedMemorySize, GSMEM_BYTES);
    cudaFuncSetAttribute((const void*)gemm_h<3, false>,
                         cudaFuncAttributeMaxDynamicSharedMemorySize, GSMEM_BYTES);

    const int MT_ROWS = B_SZ * T_SZ;  // 16384
    const dim3 blk(256);
    const long long sTE = (long long)T_SZ * E_SZ;
    const long long sTT = (long long)T_SZ * T_SZ;
    const long long sET = (long long)E_SZ * T_SZ;
    const long long sEE = (long long)E_SZ * E_SZ;
    const int KC = HE_SZ / NSPLIT;  // 512

    // --- pre-pass ---
    {
        const int nin4 = MT_ROWS * E_SZ / 4;
        const int nw4 = E_SZ * HE_SZ / 4;
        copy_f2h4<<<dim3((nin4 + 255) / 256, 4), 256>>>(
            (const float4*)query, qh, (const float4*)key, kh,
            (const float4*)value, vh, (const float4*)Wo, Woh, nin4, nw4);
        transpose32h3<<<dim3(HE_SZ / 32, E_SZ / 32, 3), dim3(32, 8)>>>(
            Wq, WqT, Wk, WkT, Wv, WvT, HE_SZ, E_SZ);
        colvec_part<<<dim3(E_SZ / 128, NCH, 2), 128>>>(Wq, bk, Wk, bq, cpart);
        colvec_red<<<dim3(E_SZ / 128, 2), 128>>>(cpart, a1, a2);
        rowvec<<<E_SZ, 256>>>(Wo, bv, wv);
        dotscalar<<<1, 256>>>(bq, bk, cs);
        dotvec2<<<dim3(MT_ROWS / 8, 2), 256>>>(query, key, a1, a2, cs, u, w);
    }

    // Merged split-K: z<8 -> M^T = WkT@WqT^T chunks; z>=8 -> P = Woh@WvT^T chunks.
    gemm_h<0, false><<<dim3(E_SZ / 256, E_SZ / 128, 2 * NSPLIT), blk, GSMEM_BYTES>>>(
        WkT, WqT, nullptr, nullptr, nullptr, part, E_SZ, KC, HE_SZ, HE_SZ, 1.f,
        KC, KC, sEE, 0, 0, Woh, WvT, NSPLIT);
    reduce_splits_h2<<<dim3((E_SZ * E_SZ / 4 + 255) / 256, 2), 256>>>(
        (float4*)part, MTh, Ph, E_SZ * E_SZ / 4);

    // qM = qh @ MTh^T   [16384,512] (half out)
    gemm_h<0, true><<<dim3(E_SZ / 256, MT_ROWS / 128, 1), blk, GSMEM_BYTES>>>(
        qh, MTh, nullptr, nullptr, nullptr, qMh, E_SZ, E_SZ, E_SZ, E_SZ, 1.f,
        0, 0, 0, 0, 0, nullptr, nullptr, 9999);
    // vpT' = Ph @ vh^T + wv[row], per batch [512,2048] (half out)
    gemm_h<2, true><<<dim3(T_SZ / 256, E_SZ / 128, B_SZ), blk, GSMEM_BYTES>>>(
        Ph, vh, wv, nullptr, nullptr, vpTh, T_SZ, E_SZ, E_SZ, E_SZ, 1.f,
        0, sTE, sET, 0, 0, nullptr, nullptr, 9999);
    // logits: atth = h( SCALE*(qMh @ kh^T + u + w) ) per batch (half out)
    gemm_h<1, true><<<dim3(T_SZ / 256, T_SZ / 128, B_SZ), blk, GSMEM_BYTES>>>(
        qMh, kh, u, w, nullptr, atth, T_SZ, E_SZ, E_SZ, E_SZ, SCALE_F,
        sTE, sTE, sTT, T_SZ, T_SZ, nullptr, nullptr, 9999);
    // batch-axis softmax in place (flat; rowsum eliminated by wv fold)
    softmax_b<<<(T_SZ * T_SZ / 4) / 256, 256>>>(atth);
    // out = atth @ vpT'^T + bo per batch (float out)
    gemm_h<3, false><<<dim3(E_SZ / 256, T_SZ / 128, B_SZ), blk, GSMEM_BYTES>>>(
        atth, vpTh, nullptr, nullptr, bo, out, E_SZ, T_SZ, T_SZ, T_SZ, 1.f,
        sTT, sET, sTE, 0, 0, nullptr, nullptr, 9999);
}